// round 11
// baseline (speedup 1.0000x reference)
#include <cuda_runtime.h>

// Problem constants
#define BB   4      // batch
#define CIN  3
#define C1   32     // conv1 out channels (16x16 spatial)
#define C2   64     // conv2 out channels (8x8 spatial)
#define MM   512    // hopfield memory slots
#define DD   64     // token dim (== C2)
#define NTOK 2      // tokens per block
#define THR  512    // threads per block
#define NBLK 128    // 4 samples x 32 token-pairs; fully independent blocks
#define LSTR 68     // Lsm row stride (floats): 17 float4, conflict-free

// Shared memory layout (float offsets)
#define LSM_OFF   0                        // 512*68 = 34816
#define WVS_OFF   34816                    // 4096
#define WOS_OFF   38912                    // 4096
#define PS2_OFF   43008                    // 512 float2 = 1024 f
#define ZQ_OFF    44032                    // [2][64] tokens / tmp
#define S1_OFF    44160                    // [2][64]
#define OS2_OFF   44288                    // 64 float2
#define RED_OFF   44416                    // 40 f reduce scratch
#define B1S_OFF   44456                    // 32 f
#define B2S_OFF   44488                    // 64 f
#define XPAD_OFF  44552                    // 3*34*34 = 3468 f (float4-aligned)
#define PART4_OFF 44552                    // 4096 f, ALIASES xpad/aW (dead by then)
#define AW_OFF    48020                    // 32*25 = 800 f
#define VW_OFF    48820                    // 32*25 = 800 f
#define W1S_OFF   49620                    // 32*3*16 = 1536 f
#define SMEM_FLOATS 51156                  // 204624 bytes

__global__ __launch_bounds__(THR, 1)
void fused_kernel(const float* __restrict__ x,
                  const float* __restrict__ w1,
                  const float* __restrict__ b1,
                  const float* __restrict__ w2,
                  const float* __restrict__ b2,
                  const float* __restrict__ lookup,
                  const float* __restrict__ Wv,
                  const float* __restrict__ Wo,
                  float* __restrict__ out) {
    extern __shared__ float smem[];
    float*  Lsm   = smem + LSM_OFF;
    float*  WvS   = smem + WVS_OFF;
    float*  WoS   = smem + WOS_OFF;
    float2* pS2   = (float2*)(smem + PS2_OFF);
    float*  zqS   = smem + ZQ_OFF;        // [j][64]: tokens, later tmp
    float*  s1S   = smem + S1_OFF;        // [j][64]: first projection
    float2* oS2   = (float2*)(smem + OS2_OFF);
    float2* red2  = (float2*)(smem + RED_OFF);
    float*  B1S   = smem + B1S_OFF;
    float*  B2S   = smem + B2S_OFF;
    float*  xpad  = smem + XPAD_OFF;      // [3][34][34] zero-padded input
    float4* part4 = (float4*)(smem + PART4_OFF);   // aliases xpad (dead)
    float*  aW    = smem + AW_OFF;        // conv1 window, relu(pre)
    float*  vW    = smem + VW_OFF;        // conv1 window, masked JVP
    float*  w1S   = smem + W1S_OFF;       // conv1 weights

    int tid  = threadIdx.x;
    int lane = tid & 31;
    int wid  = tid >> 5;
    int blk  = blockIdx.x;
    int b    = blk >> 5;                  // sample
    int tg   = blk & 31;                  // token group
    int n0   = tg * NTOK;
    int oy   = n0 >> 3;                   // both tokens share oy (n0 even)
    int ox0  = n0 & 7;

    // ===== Stage 0a: zero the padded x tile ================================
    #pragma unroll
    for (int it = 0; it < 7; it++) {
        int i = it*THR + tid;
        if (i < 3*34*34) xpad[i] = 0.f;
    }
    __syncthreads();

    // ===== Stage 0b: lookup (MLP=8), Wv/Wo, x interior, w1, b1, b2 =========
    {
        const float4* L4   = (const float4*)lookup;
        float4*       Lsm4 = (float4*)Lsm;         // row stride 17 float4
        #pragma unroll
        for (int batch = 0; batch < 2; batch++) {
            float4 v[8];
            #pragma unroll
            for (int u = 0; u < 8; u++)
                v[u] = __ldg(&L4[(batch*8 + u)*THR + tid]);
            #pragma unroll
            for (int u = 0; u < 8; u++) {
                int f = (batch*8 + u)*THR + tid;   // float4 index
                Lsm4[(f >> 4)*17 + (f & 15)] = v[u];
            }
        }
    }
    {
        const float4* Wv4 = (const float4*)Wv;
        const float4* Wo4 = (const float4*)Wo;
        ((float4*)WvS)[tid]       = __ldg(&Wv4[tid]);
        ((float4*)WvS)[tid + THR] = __ldg(&Wv4[tid + THR]);
        ((float4*)WoS)[tid]       = __ldg(&Wo4[tid]);
        ((float4*)WoS)[tid + THR] = __ldg(&Wo4[tid + THR]);
    }
    {
        const float* xb = x + b * CIN * 1024;
        #pragma unroll
        for (int it = 0; it < 6; it++) {
            int i = it*THR + tid;                  // < 3072
            int ic = i >> 10, r = (i >> 5) & 31, c = i & 31;
            xpad[(ic*34 + r + 1)*34 + c + 1] = __ldg(&xb[i]);
        }
    }
    if (tid < 384)                                 // 1536 f = 384 float4
        ((float4*)w1S)[tid] = __ldg(&((const float4*)w1)[tid]);
    if (tid < 96) {
        if (tid < 32) B1S[tid] = __ldg(&b1[tid]);
        else          B2S[tid - 32] = __ldg(&b2[tid - 32]);
    }
    __syncthreads();

    // ===== Phase 1: conv1 for the 4x6 window this block needs ==============
    for (int e = tid; e < 32*24; e += THR) {
        int ic  = e / 24;
        int pos = e - ic*24;
        int ri  = pos / 6;
        int ci  = pos - ri*6;
        int r = 2*oy - 1 + ri;
        int c = 2*ox0 - 1 + ci;
        float aVal = 0.f, vVal = 0.f;
        if ((unsigned)r < 16u && (unsigned)c < 16u) {
            float s = 0.f;
            #pragma unroll
            for (int cin = 0; cin < CIN; cin++) {
                const float* base = &xpad[(cin*34 + 2*r)*34 + 2*c];
                const float4* wp4 = (const float4*)&w1S[(ic*CIN + cin)*16];
                #pragma unroll
                for (int ky = 0; ky < 4; ky++) {
                    float4 w4 = wp4[ky];
                    const float* row = base + ky*34;
                    s += row[0]*w4.x + row[1]*w4.y + row[2]*w4.z + row[3]*w4.w;
                }
            }
            float pre = s + B1S[ic];
            if (pre > 0.f) { aVal = pre; vVal = s; }
        }
        aW[ic*25 + pos] = aVal;
        vW[ic*25 + pos] = vVal;
    }
    __syncthreads();

    // ===== Phase 2: conv2.  thread = (oc, ic-octet), computes BOTH tokens ==
    {
        int oc  = tid >> 3;          // 0..63
        int ich = tid & 7;           // ic octet (low bits -> shfl-local)
        float sA0 = 0.f, sV0 = 0.f, sA1 = 0.f, sV1 = 0.f;
        #pragma unroll
        for (int i = 0; i < 4; i++) {
            int ic = ich*4 + i;
            const float*  ar  = &aW[ic*25];
            const float*  vr  = &vW[ic*25];
            const float4* wp4 = (const float4*)&w2[(oc*C1 + ic)*16];
            #pragma unroll
            for (int ky = 0; ky < 4; ky++) {
                float4 w4 = __ldg(&wp4[ky]);
                const float* a = &ar[ky*6];
                const float* v = &vr[ky*6];
                float a0=a[0],a1=a[1],a2=a[2],a3=a[3],a4=a[4],a5=a[5];
                float v0=v[0],v1=v[1],v2=v[2],v3=v[3],v4=v[4],v5=v[5];
                sA0 += a0*w4.x + a1*w4.y + a2*w4.z + a3*w4.w;
                sV0 += v0*w4.x + v1*w4.y + v2*w4.z + v3*w4.w;
                sA1 += a2*w4.x + a3*w4.y + a4*w4.z + a5*w4.w;
                sV1 += v2*w4.x + v3*w4.y + v4*w4.z + v5*w4.w;
            }
        }
        #pragma unroll
        for (int off = 1; off <= 4; off <<= 1) {
            sA0 += __shfl_xor_sync(0xFFFFFFFFu, sA0, off);
            sV0 += __shfl_xor_sync(0xFFFFFFFFu, sV0, off);
            sA1 += __shfl_xor_sync(0xFFFFFFFFu, sA1, off);
            sV1 += __shfl_xor_sync(0xFFFFFFFFu, sV1, off);
        }
        if (ich == 0) {
            float bb = B2S[oc];
            float p0 = sA0 + bb;
            float p1 = sA1 + bb;
            zqS[oc]      = (p0 > 0.f) ? sV0 : 0.f;
            zqS[DD + oc] = (p1 > 0.f) ? sV1 : 0.f;
        }
    }
    __syncthreads();

    // ===== Phase 3: hopfield ==============================================
    // scores: thread owns row m = tid, both tokens
    float a0 = 0.f, a1 = 0.f;
    {
        const float4* lrow = (const float4*)&Lsm[tid*LSTR];
        const float4* t0p  = (const float4*)&zqS[0];
        const float4* t1p  = (const float4*)&zqS[DD];
        #pragma unroll
        for (int q = 0; q < 16; q++) {
            float4 l  = lrow[q];
            float4 t0 = t0p[q];
            float4 t1 = t1p[q];
            a0 += l.x*t0.x + l.y*t0.y + l.z*t0.z + l.w*t0.w;
            a1 += l.x*t1.x + l.y*t1.y + l.z*t1.z + l.w*t1.w;
        }
    }
    a0 *= 0.125f; a1 *= 0.125f;   // 1/sqrt(64)

    // block max
    {
        float mx0 = a0, mx1 = a1;
        #pragma unroll
        for (int o = 16; o > 0; o >>= 1) {
            mx0 = fmaxf(mx0, __shfl_xor_sync(0xFFFFFFFFu, mx0, o));
            mx1 = fmaxf(mx1, __shfl_xor_sync(0xFFFFFFFFu, mx1, o));
        }
        if (lane == 0) red2[wid] = make_float2(mx0, mx1);
    }
    __syncthreads();
    if (tid < 32) {
        float2 v = (lane < 16) ? red2[lane] : make_float2(-1e30f, -1e30f);
        #pragma unroll
        for (int o = 8; o > 0; o >>= 1) {
            v.x = fmaxf(v.x, __shfl_xor_sync(0xFFFFFFFFu, v.x, o));
            v.y = fmaxf(v.y, __shfl_xor_sync(0xFFFFFFFFu, v.y, o));
        }
        if (lane == 0) red2[16] = v;
    }
    __syncthreads();
    float2 MX = red2[16];

    // exp + block sum
    float e0 = __expf(a0 - MX.x);
    float e1 = __expf(a1 - MX.y);
    pS2[tid] = make_float2(e0, e1);
    {
        float s0 = e0, s1 = e1;
        #pragma unroll
        for (int o = 16; o > 0; o >>= 1) {
            s0 += __shfl_xor_sync(0xFFFFFFFFu, s0, o);
            s1 += __shfl_xor_sync(0xFFFFFFFFu, s1, o);
        }
        if (lane == 0) red2[wid] = make_float2(s0, s1);
    }
    __syncthreads();
    if (tid < 32) {
        float2 v = (lane < 16) ? red2[lane] : make_float2(0.f, 0.f);
        #pragma unroll
        for (int o = 8; o > 0; o >>= 1) {
            v.x += __shfl_xor_sync(0xFFFFFFFFu, v.x, o);
            v.y += __shfl_xor_sync(0xFFFFFFFFu, v.y, o);
        }
        if (lane == 0) red2[17] = v;
    }
    __syncthreads();
    float2 SUM = red2[17];

    // retrieval, stage 1: thread = (c, d4); c = 32 chunks of 16 m, d4 = 16
    // float4 column groups. LDS.128 row reads, broadcast p reads.
    {
        int d4 = tid & 15;
        int c  = tid >> 4;
        const float4* Lsm4 = (const float4*)Lsm;
        float4 r0 = make_float4(0.f, 0.f, 0.f, 0.f);
        float4 r1 = make_float4(0.f, 0.f, 0.f, 0.f);
        int m0 = c * 16;
        #pragma unroll
        for (int mm = 0; mm < 16; mm++) {
            float2 p = pS2[m0 + mm];                    // broadcast
            float4 l = Lsm4[(m0 + mm)*17 + d4];         // LDS.128
            r0.x += p.x*l.x; r0.y += p.x*l.y; r0.z += p.x*l.z; r0.w += p.x*l.w;
            r1.x += p.y*l.x; r1.y += p.y*l.y; r1.z += p.y*l.z; r1.w += p.y*l.w;
        }
        part4[(c*2 + 0)*16 + d4] = r0;
        part4[(c*2 + 1)*16 + d4] = r1;
    }
    __syncthreads();
    // retrieval, stage 2: thread = (j, d) sums 32 chunks
    if (tid < NTOK*DD) {
        int j = tid >> 6, d = tid & 63;
        const float* pf = (const float*)part4;          // [(c*2+j)*64 + d]
        float s = 0.f;
        #pragma unroll
        for (int c = 0; c < 32; c++)
            s += pf[(c*2 + j)*64 + d];
        float inv = 1.f / (j ? SUM.y : SUM.x);
        zqS[j*DD + d] = s * inv;                        // tmp[j][d]
    }
    __syncthreads();

    // projection 1: s1[j][f] = sum_d tmp[j][d] * Wv[d][f]
    if (tid < NTOK*DD) {
        int j = tid >> 6, f = tid & 63;
        float s = 0.f;
        const float* tp = &zqS[j*DD];
        #pragma unroll 16
        for (int d = 0; d < DD; d++)
            s += tp[d] * WvS[d*DD + f];           // bcast + conflict-free
        s1S[j*DD + f] = s;
    }
    __syncthreads();

    // projection 2: out[j][e] = sum_f s1[j][f] * Wo[f][e]
    if (tid < NTOK*DD) {
        int j = tid >> 6, e = tid & 63;
        float o = 0.f;
        const float* sp = &s1S[j*DD];
        #pragma unroll 16
        for (int f = 0; f < DD; f++)
            o += sp[f] * WoS[f*DD + e];
        ((float*)&oS2[e])[j] = o;
    }
    __syncthreads();
    if (tid < DD) {
        float2 ov = oS2[tid];
        *(float2*)&out[(b*C2 + tid)*64 + n0] = ov;
    }
}

// ---------------------------------------------------------------------------
extern "C" void kernel_launch(void* const* d_in, const int* in_sizes, int n_in,
                              void* d_out, int out_size) {
    const float* x       = (const float*)d_in[0];
    const float* conv1_w = (const float*)d_in[1];
    const float* conv1_b = (const float*)d_in[2];
    const float* conv2_w = (const float*)d_in[3];
    const float* conv2_b = (const float*)d_in[4];
    const float* lookup  = (const float*)d_in[5];
    const float* Wv      = (const float*)d_in[6];
    const float* Wo      = (const float*)d_in[7];
    float* out = (float*)d_out;

    const size_t smem_bytes = SMEM_FLOATS * sizeof(float);

    cudaFuncSetAttribute(fused_kernel,
                         cudaFuncAttributeMaxDynamicSharedMemorySize,
                         (int)smem_bytes);
    cudaFuncSetAttribute(fused_kernel,
                         cudaFuncAttributePreferredSharedMemoryCarveout, 100);

    fused_kernel<<<NBLK, THR, smem_bytes>>>(
        x, conv1_w, conv1_b, conv2_w, conv2_b, lookup, Wv, Wo, out);
}

// round 12
// speedup vs baseline: 1.3908x; 1.3908x over previous
#include <cuda_runtime.h>

// Problem constants
#define BB   4      // batch
#define CIN  3
#define C1   32     // conv1 out channels (16x16 spatial)
#define C2   64     // conv2 out channels (8x8 spatial)
#define MM   512    // hopfield memory slots
#define DD   64     // token dim (== C2)
#define NTOK 2      // tokens per block
#define THR  512    // threads per block
#define NBLK 128    // 4 samples x 32 token-pairs; fully independent blocks
#define LSTR 68     // Lsm row stride (floats): 16B-aligned, conflict-free

// Shared memory layout (float offsets) — identical to the 17.5us baseline.
#define LSM_OFF   0                        // 512*68 = 34816
#define WVS_OFF   34816                    // 64*64  = 4096
#define WOS_OFF   38912                    // 64*64  = 4096
#define PS2_OFF   43008                    // 512 float2 = 1024 f
#define PART2_OFF 44032                    // 512 float2 = 1024 f
#define ZQ_OFF    45056                    // [2][64] tokens / tmp = 128 f
#define S1_OFF    45184                    // [2][64] = 128 f
#define OS2_OFF   45312                    // 64 float2 = 128 f
#define RED_OFF   45440                    // 40 f reduce scratch
#define XPAD_OFF  45480                    // 3*34*34 = 3468 f
#define AW_OFF    48948                    // 32*25 = 800 f (stride-25 conflict-free)
#define VW_OFF    49748                    // 32*25 = 800 f
#define SMEM_FLOATS 50548                  // 202192 bytes

__global__ __launch_bounds__(THR, 1)
void fused_kernel(const float* __restrict__ x,
                  const float* __restrict__ w1,
                  const float* __restrict__ b1,
                  const float* __restrict__ w2,
                  const float* __restrict__ b2,
                  const float* __restrict__ lookup,
                  const float* __restrict__ Wv,
                  const float* __restrict__ Wo,
                  float* __restrict__ out) {
    extern __shared__ float smem[];
    float*  Lsm   = smem + LSM_OFF;
    float*  WvS   = smem + WVS_OFF;
    float*  WoS   = smem + WOS_OFF;
    float2* pS2   = (float2*)(smem + PS2_OFF);
    float2* part2 = (float2*)(smem + PART2_OFF);
    float*  zqS   = smem + ZQ_OFF;        // [j][64]: tokens, later tmp
    float*  s1S   = smem + S1_OFF;        // [j][64]: first projection
    float2* oS2   = (float2*)(smem + OS2_OFF);
    float2* red2  = (float2*)(smem + RED_OFF);
    float*  xpad  = smem + XPAD_OFF;      // [3][34][34] zero-padded input
    float*  aW    = smem + AW_OFF;        // conv1 window, relu(pre)
    float*  vW    = smem + VW_OFF;        // conv1 window, masked JVP

    int tid  = threadIdx.x;
    int lane = tid & 31;
    int wid  = tid >> 5;
    int blk  = blockIdx.x;
    int b    = blk >> 5;                  // sample
    int tg   = blk & 31;                  // token group
    int n0   = tg * NTOK;
    int oy   = n0 >> 3;                   // both tokens share oy (n0 even)
    int ox0  = n0 & 7;

    // ===== Stage 0a: zero the padded x tile ================================
    #pragma unroll
    for (int it = 0; it < 7; it++) {
        int i = it*THR + tid;
        if (i < 3*34*34) xpad[i] = 0.f;
    }
    __syncthreads();

    // ===== Stage 0b: lookup -> Lsm (MLP=8), Wv/Wo -> smem, x[b] interior ===
    {
        const float4* L4   = (const float4*)lookup;
        float4*       Lsm4 = (float4*)Lsm;         // row stride 17 float4
        #pragma unroll
        for (int batch = 0; batch < 2; batch++) {
            float4 v[8];
            #pragma unroll
            for (int u = 0; u < 8; u++)
                v[u] = __ldg(&L4[(batch*8 + u)*THR + tid]);
            #pragma unroll
            for (int u = 0; u < 8; u++) {
                int f = (batch*8 + u)*THR + tid;   // float4 index
                Lsm4[(f >> 4)*17 + (f & 15)] = v[u];
            }
        }
    }
    {
        const float4* Wv4 = (const float4*)Wv;
        const float4* Wo4 = (const float4*)Wo;
        ((float4*)WvS)[tid]       = __ldg(&Wv4[tid]);
        ((float4*)WvS)[tid + THR] = __ldg(&Wv4[tid + THR]);
        ((float4*)WoS)[tid]       = __ldg(&Wo4[tid]);
        ((float4*)WoS)[tid + THR] = __ldg(&Wo4[tid + THR]);
    }
    {
        const float* xb = x + b * CIN * 1024;
        #pragma unroll
        for (int it = 0; it < 6; it++) {
            int i = it*THR + tid;                  // < 3072
            int ic = i >> 10, r = (i >> 5) & 31, c = i & 31;
            xpad[(ic*34 + r + 1)*34 + c + 1] = __ldg(&xb[i]);
        }
    }
    __syncthreads();

    // ===== Phase 1: conv1 for just the 4x6 window this block needs =========
    for (int e = tid; e < 32*24; e += THR) {
        int ic  = e / 24;
        int pos = e - ic*24;
        int ri  = pos / 6;
        int ci  = pos - ri*6;
        int r = 2*oy - 1 + ri;
        int c = 2*ox0 - 1 + ci;
        float aVal = 0.f, vVal = 0.f;
        if ((unsigned)r < 16u && (unsigned)c < 16u) {
            float s = 0.f;
            #pragma unroll
            for (int cin = 0; cin < CIN; cin++) {
                const float* base = &xpad[(cin*34 + 2*r)*34 + 2*c];
                const float4* wp4 = (const float4*)&w1[(ic*CIN + cin)*16];
                #pragma unroll
                for (int ky = 0; ky < 4; ky++) {
                    float4 w4 = __ldg(&wp4[ky]);
                    const float* row = base + ky*34;
                    s += row[0]*w4.x + row[1]*w4.y + row[2]*w4.z + row[3]*w4.w;
                }
            }
            float pre = s + __ldg(&b1[ic]);
            if (pre > 0.f) { aVal = pre; vVal = s; }
        }
        aW[ic*25 + pos] = aVal;
        vW[ic*25 + pos] = vVal;
    }
    __syncthreads();

    // ===== Phase 2: conv2.  thread = (oc, ic-octet), computes BOTH tokens ==
    // 12 shuffles total instead of the 80 in the warp-per-4-oc scheme.
    {
        int oc  = tid >> 3;          // 0..63
        int ich = tid & 7;           // ic octet (low bits -> shfl-local)
        float sA0 = 0.f, sV0 = 0.f, sA1 = 0.f, sV1 = 0.f;
        #pragma unroll
        for (int i = 0; i < 4; i++) {
            int ic = ich*4 + i;
            const float*  ar  = &aW[ic*25];
            const float*  vr  = &vW[ic*25];
            const float4* wp4 = (const float4*)&w2[(oc*C1 + ic)*16];
            #pragma unroll
            for (int ky = 0; ky < 4; ky++) {
                float4 w4 = __ldg(&wp4[ky]);
                const float* a = &ar[ky*6];
                const float* v = &vr[ky*6];
                float a0=a[0],a1=a[1],a2=a[2],a3=a[3],a4=a[4],a5=a[5];
                float v0=v[0],v1=v[1],v2=v[2],v3=v[3],v4=v[4],v5=v[5];
                sA0 += a0*w4.x + a1*w4.y + a2*w4.z + a3*w4.w;
                sV0 += v0*w4.x + v1*w4.y + v2*w4.z + v3*w4.w;
                sA1 += a2*w4.x + a3*w4.y + a4*w4.z + a5*w4.w;
                sV1 += v2*w4.x + v3*w4.y + v4*w4.z + v5*w4.w;
            }
        }
        #pragma unroll
        for (int off = 1; off <= 4; off <<= 1) {
            sA0 += __shfl_xor_sync(0xFFFFFFFFu, sA0, off);
            sV0 += __shfl_xor_sync(0xFFFFFFFFu, sV0, off);
            sA1 += __shfl_xor_sync(0xFFFFFFFFu, sA1, off);
            sV1 += __shfl_xor_sync(0xFFFFFFFFu, sV1, off);
        }
        if (ich == 0) {
            float bb = __ldg(&b2[oc]);
            float p0 = sA0 + bb;
            float p1 = sA1 + bb;
            zqS[oc]      = (p0 > 0.f) ? sV0 : 0.f;
            zqS[DD + oc] = (p1 > 0.f) ? sV1 : 0.f;
        }
    }
    __syncthreads();

    // ===== Phase 3: hopfield ==============================================
    // scores: thread owns row m = tid, both tokens
    float a0 = 0.f, a1 = 0.f;
    {
        const float4* lrow = (const float4*)&Lsm[tid*LSTR];
        const float4* t0p  = (const float4*)&zqS[0];
        const float4* t1p  = (const float4*)&zqS[DD];
        #pragma unroll
        for (int q = 0; q < 16; q++) {
            float4 l  = lrow[q];
            float4 t0 = t0p[q];
            float4 t1 = t1p[q];
            a0 += l.x*t0.x + l.y*t0.y + l.z*t0.z + l.w*t0.w;
            a1 += l.x*t1.x + l.y*t1.y + l.z*t1.z + l.w*t1.w;
        }
    }
    a0 *= 0.125f; a1 *= 0.125f;   // 1/sqrt(64)

    // block max
    {
        float mx0 = a0, mx1 = a1;
        #pragma unroll
        for (int o = 16; o > 0; o >>= 1) {
            mx0 = fmaxf(mx0, __shfl_xor_sync(0xFFFFFFFFu, mx0, o));
            mx1 = fmaxf(mx1, __shfl_xor_sync(0xFFFFFFFFu, mx1, o));
        }
        if (lane == 0) red2[wid] = make_float2(mx0, mx1);
    }
    __syncthreads();
    if (tid < 32) {
        float2 v = (lane < 16) ? red2[lane] : make_float2(-1e30f, -1e30f);
        #pragma unroll
        for (int o = 8; o > 0; o >>= 1) {
            v.x = fmaxf(v.x, __shfl_xor_sync(0xFFFFFFFFu, v.x, o));
            v.y = fmaxf(v.y, __shfl_xor_sync(0xFFFFFFFFu, v.y, o));
        }
        if (lane == 0) red2[16] = v;
    }
    __syncthreads();
    float2 MX = red2[16];

    // exp + block sum
    float e0 = __expf(a0 - MX.x);
    float e1 = __expf(a1 - MX.y);
    pS2[tid] = make_float2(e0, e1);
    {
        float s0 = e0, s1 = e1;
        #pragma unroll
        for (int o = 16; o > 0; o >>= 1) {
            s0 += __shfl_xor_sync(0xFFFFFFFFu, s0, o);
            s1 += __shfl_xor_sync(0xFFFFFFFFu, s1, o);
        }
        if (lane == 0) red2[wid] = make_float2(s0, s1);
    }
    __syncthreads();
    if (tid < 32) {
        float2 v = (lane < 16) ? red2[lane] : make_float2(0.f, 0.f);
        #pragma unroll
        for (int o = 8; o > 0; o >>= 1) {
            v.x += __shfl_xor_sync(0xFFFFFFFFu, v.x, o);
            v.y += __shfl_xor_sync(0xFFFFFFFFu, v.y, o);
        }
        if (lane == 0) red2[17] = v;
    }
    __syncthreads();
    float2 SUM = red2[17];

    // retrieval: part[c][d] = sum over 64 m of p[m]*L[m][d]  (R9 shape)
    {
        int d = tid & 63, c = tid >> 6;   // 8 chunks of 64 m
        float r0 = 0.f, r1 = 0.f;
        int m0 = c * 64;
        #pragma unroll 8
        for (int mm = 0; mm < 64; mm++) {
            float2 p = pS2[m0 + mm];              // broadcast
            float  l = Lsm[(m0 + mm)*LSTR + d];   // conflict-free
            r0 += p.x*l; r1 += p.y*l;
        }
        part2[c*64 + d] = make_float2(r0, r1);
    }
    __syncthreads();
    if (tid < NTOK*DD) {
        int j = tid >> 6, d = tid & 63;
        const float* pf = (const float*)part2;
        float s = 0.f;
        #pragma unroll
        for (int c = 0; c < 8; c++)
            s += pf[(c*64 + d)*2 + j];
        float inv = 1.f / (j ? SUM.y : SUM.x);
        zqS[j*DD + d] = s * inv;                  // tmp[j][d] (zqS reused)
    }
    __syncthreads();

    // projection 1: s1[j][f] = sum_d tmp[j][d] * Wv[d][f]
    if (tid < NTOK*DD) {
        int j = tid >> 6, f = tid & 63;
        float s = 0.f;
        const float* tp = &zqS[j*DD];
        #pragma unroll 16
        for (int d = 0; d < DD; d++)
            s += tp[d] * WvS[d*DD + f];           // bcast + conflict-free
        s1S[j*DD + f] = s;
    }
    __syncthreads();

    // projection 2: out[j][e] = sum_f s1[j][f] * Wo[f][e]
    if (tid < NTOK*DD) {
        int j = tid >> 6, e = tid & 63;
        float o = 0.f;
        const float* sp = &s1S[j*DD];
        #pragma unroll 16
        for (int f = 0; f < DD; f++)
            o += sp[f] * WoS[f*DD + e];
        ((float*)&oS2[e])[j] = o;
    }
    __syncthreads();
    if (tid < DD) {
        float2 ov = oS2[tid];
        *(float2*)&out[(b*C2 + tid)*64 + n0] = ov;
    }
}

// ---------------------------------------------------------------------------
extern "C" void kernel_launch(void* const* d_in, const int* in_sizes, int n_in,
                              void* d_out, int out_size) {
    const float* x       = (const float*)d_in[0];
    const float* conv1_w = (const float*)d_in[1];
    const float* conv1_b = (const float*)d_in[2];
    const float* conv2_w = (const float*)d_in[3];
    const float* conv2_b = (const float*)d_in[4];
    const float* lookup  = (const float*)d_in[5];
    const float* Wv      = (const float*)d_in[6];
    const float* Wo      = (const float*)d_in[7];
    float* out = (float*)d_out;

    const size_t smem_bytes = SMEM_FLOATS * sizeof(float);

    cudaFuncSetAttribute(fused_kernel,
                         cudaFuncAttributeMaxDynamicSharedMemorySize,
                         (int)smem_bytes);
    cudaFuncSetAttribute(fused_kernel,
                         cudaFuncAttributePreferredSharedMemoryCarveout, 100);

    fused_kernel<<<NBLK, THR, smem_bytes>>>(
        x, conv1_w, conv1_b, conv2_w, conv2_b, lookup, Wv, Wo, out);
}

// round 13
// speedup vs baseline: 1.6996x; 1.2220x over previous
#include <cuda_runtime.h>

// Problem constants
#define BB   4      // batch
#define CIN  3
#define C1   32     // conv1 out channels (16x16 spatial)
#define C2   64     // conv2 out channels (8x8 spatial)
#define MM   512    // hopfield memory slots
#define DD   64     // token dim (== C2)
#define NTOK 2      // tokens per block
#define THR  512    // threads per block
#define NBLK 128    // 4 samples x 32 token-pairs; fully independent blocks
#define LSTR 68     // Lsm row stride (floats): 16B-aligned, conflict-free

// Shared memory layout (float offsets) — identical to the 17.5us baseline.
#define LSM_OFF   0                        // 512*68 = 34816
#define WVS_OFF   34816                    // 64*64  = 4096
#define WOS_OFF   38912                    // 64*64  = 4096
#define PS2_OFF   43008                    // 512 float2 = 1024 f
#define PART2_OFF 44032                    // 512 float2 = 1024 f
#define ZQ_OFF    45056                    // [2][64] tokens / tmp = 128 f
#define S1_OFF    45184                    // [2][64] = 128 f
#define OS2_OFF   45312                    // 64 float2 = 128 f
#define RED_OFF   45440                    // 40 f reduce scratch
#define XPAD_OFF  45480                    // 3*34*34 = 3468 f
#define AW_OFF    48948                    // 32*25 = 800 f (stride-25 conflict-free)
#define VW_OFF    49748                    // 32*25 = 800 f
#define SMEM_FLOATS 50548                  // 202192 bytes

__global__ __launch_bounds__(THR, 1)
void fused_kernel(const float* __restrict__ x,
                  const float* __restrict__ w1,
                  const float* __restrict__ b1,
                  const float* __restrict__ w2,
                  const float* __restrict__ b2,
                  const float* __restrict__ lookup,
                  const float* __restrict__ Wv,
                  const float* __restrict__ Wo,
                  float* __restrict__ out) {
    extern __shared__ float smem[];
    float*  Lsm   = smem + LSM_OFF;
    float*  WvS   = smem + WVS_OFF;
    float*  WoS   = smem + WOS_OFF;
    float2* pS2   = (float2*)(smem + PS2_OFF);
    float2* part2 = (float2*)(smem + PART2_OFF);
    float*  zqS   = smem + ZQ_OFF;        // [j][64]: tokens, later tmp
    float*  s1S   = smem + S1_OFF;        // [j][64]: first projection
    float2* oS2   = (float2*)(smem + OS2_OFF);
    float2* red2  = (float2*)(smem + RED_OFF);
    float*  xpad  = smem + XPAD_OFF;      // [3][34][34] zero-padded input
    float*  aW    = smem + AW_OFF;        // conv1 window, relu(pre)
    float*  vW    = smem + VW_OFF;        // conv1 window, masked JVP

    int tid  = threadIdx.x;
    int lane = tid & 31;
    int wid  = tid >> 5;
    int blk  = blockIdx.x;
    int b    = blk >> 5;                  // sample
    int tg   = blk & 31;                  // token group
    int n0   = tg * NTOK;
    int oy   = n0 >> 3;                   // both tokens share oy (n0 even)
    int ox0  = n0 & 7;

    // ===================================================================
    // Warp-specialized front end:
    //   warps 0-7  (tid < 256): xpad halo-zero + interior stage + conv1
    //   warps 8-15 (tid >= 256): Lsm + Wv + Wo staging
    // Joined by one __syncthreads before conv2.
    // ===================================================================
    if (tid < 256) {
        // --- halo-only zero (396 cells; disjoint from interior writes) ---
        for (int i = tid; i < 396; i += 256) {
            int p = i / 132, rem = i - p*132;
            int r, c;
            if (rem < 68) { r = (rem < 34) ? 0 : 33;
                            c = (rem < 34) ? rem : rem - 34; }
            else { int q = rem - 68; r = 1 + (q >> 1); c = (q & 1) * 33; }
            xpad[(p*34 + r)*34 + c] = 0.f;
        }
        // --- interior stage: 3072 floats / 256 threads = 12 each ---
        {
            const float* xb = x + b * CIN * 1024;
            #pragma unroll
            for (int it = 0; it < 12; it++) {
                int i = it*256 + tid;
                int ic = i >> 10, r = (i >> 5) & 31, c = i & 31;
                xpad[(ic*34 + r + 1)*34 + c + 1] = __ldg(&xb[i]);
            }
        }
        // conv-group barrier: warps 0-7 only (256 threads)
        asm volatile("bar.sync 1, 256;" ::: "memory");

        // --- Phase 1: conv1 for the 4x6 window (R9 body, stride 256) ---
        for (int e = tid; e < 32*24; e += 256) {
            int ic  = e / 24;
            int pos = e - ic*24;
            int ri  = pos / 6;
            int ci  = pos - ri*6;
            int r = 2*oy - 1 + ri;
            int c = 2*ox0 - 1 + ci;
            float aVal = 0.f, vVal = 0.f;
            if ((unsigned)r < 16u && (unsigned)c < 16u) {
                float s = 0.f;
                #pragma unroll
                for (int cin = 0; cin < CIN; cin++) {
                    const float* base = &xpad[(cin*34 + 2*r)*34 + 2*c];
                    const float4* wp4 = (const float4*)&w1[(ic*CIN + cin)*16];
                    #pragma unroll
                    for (int ky = 0; ky < 4; ky++) {
                        float4 w4 = __ldg(&wp4[ky]);
                        const float* row = base + ky*34;
                        s += row[0]*w4.x + row[1]*w4.y + row[2]*w4.z + row[3]*w4.w;
                    }
                }
                float pre = s + __ldg(&b1[ic]);
                if (pre > 0.f) { aVal = pre; vVal = s; }
            }
            aW[ic*25 + pos] = aVal;
            vW[ic*25 + pos] = vVal;
        }
    } else {
        int t2 = tid - 256;                        // 0..255
        // --- Lsm staging: 8192 float4 / 256 thr = 32 each, MLP=8 batches ---
        const float4* L4   = (const float4*)lookup;
        float4*       Lsm4 = (float4*)Lsm;         // row stride 17 float4
        #pragma unroll
        for (int batch = 0; batch < 4; batch++) {
            float4 v[8];
            #pragma unroll
            for (int u = 0; u < 8; u++)
                v[u] = __ldg(&L4[(batch*8 + u)*256 + t2]);
            #pragma unroll
            for (int u = 0; u < 8; u++) {
                int f = (batch*8 + u)*256 + t2;    // float4 index
                Lsm4[(f >> 4)*17 + (f & 15)] = v[u];
            }
        }
        // --- Wv / Wo staging: 1024 float4 each / 256 thr = 4 each ---
        {
            const float4* Wv4 = (const float4*)Wv;
            const float4* Wo4 = (const float4*)Wo;
            #pragma unroll
            for (int u = 0; u < 4; u++) {
                ((float4*)WvS)[u*256 + t2] = __ldg(&Wv4[u*256 + t2]);
                ((float4*)WoS)[u*256 + t2] = __ldg(&Wo4[u*256 + t2]);
            }
        }
    }
    __syncthreads();

    // ===== Phase 2: conv2 (EXACT R9 shape: warp->4 oc, lane->ic) ==========
    {
        int ic = lane;
        float sA[4][2] = {}, sV[4][2] = {};
        const float4* w24 = (const float4*)w2;
        #pragma unroll
        for (int ky = 0; ky < 4; ky++) {
            const float* ar = &aW[ic*25 + ky*6];
            const float* vr = &vW[ic*25 + ky*6];
            float a0=ar[0], a1=ar[1], a2=ar[2], a3=ar[3], a4=ar[4], a5=ar[5];
            float v0=vr[0], v1=vr[1], v2=vr[2], v3=vr[3], v4=vr[4], v5=vr[5];
            #pragma unroll
            for (int o4 = 0; o4 < 4; o4++) {
                float4 w4 = __ldg(&w24[((wid*4 + o4)*C1 + ic)*4 + ky]);
                sA[o4][0] += a0*w4.x + a1*w4.y + a2*w4.z + a3*w4.w;
                sV[o4][0] += v0*w4.x + v1*w4.y + v2*w4.z + v3*w4.w;
                sA[o4][1] += a2*w4.x + a3*w4.y + a4*w4.z + a5*w4.w;
                sV[o4][1] += v2*w4.x + v3*w4.y + v4*w4.z + v5*w4.w;
            }
        }
        #pragma unroll
        for (int o4 = 0; o4 < 4; o4++)
            #pragma unroll
            for (int jj = 0; jj < 2; jj++)
                #pragma unroll
                for (int off = 16; off > 0; off >>= 1) {
                    sA[o4][jj] += __shfl_xor_sync(0xFFFFFFFFu, sA[o4][jj], off);
                    sV[o4][jj] += __shfl_xor_sync(0xFFFFFFFFu, sV[o4][jj], off);
                }
        if (lane == 0) {
            #pragma unroll
            for (int o4 = 0; o4 < 4; o4++) {
                int oc = wid*4 + o4;
                float bb = __ldg(&b2[oc]);
                #pragma unroll
                for (int jj = 0; jj < 2; jj++) {
                    float pre = sA[o4][jj] + bb;
                    zqS[jj*DD + oc] = (pre > 0.f) ? sV[o4][jj] : 0.f;
                }
            }
        }
    }
    __syncthreads();

    // ===== Phase 3: hopfield (EXACT R9) ===================================
    // scores: thread owns row m = tid, both tokens
    float a0 = 0.f, a1 = 0.f;
    {
        const float4* lrow = (const float4*)&Lsm[tid*LSTR];
        const float4* t0p  = (const float4*)&zqS[0];
        const float4* t1p  = (const float4*)&zqS[DD];
        #pragma unroll
        for (int q = 0; q < 16; q++) {
            float4 l  = lrow[q];
            float4 t0 = t0p[q];
            float4 t1 = t1p[q];
            a0 += l.x*t0.x + l.y*t0.y + l.z*t0.z + l.w*t0.w;
            a1 += l.x*t1.x + l.y*t1.y + l.z*t1.z + l.w*t1.w;
        }
    }
    a0 *= 0.125f; a1 *= 0.125f;   // 1/sqrt(64)

    // block max
    {
        float mx0 = a0, mx1 = a1;
        #pragma unroll
        for (int o = 16; o > 0; o >>= 1) {
            mx0 = fmaxf(mx0, __shfl_xor_sync(0xFFFFFFFFu, mx0, o));
            mx1 = fmaxf(mx1, __shfl_xor_sync(0xFFFFFFFFu, mx1, o));
        }
        if (lane == 0) red2[wid] = make_float2(mx0, mx1);
    }
    __syncthreads();
    if (tid < 32) {
        float2 v = (lane < 16) ? red2[lane] : make_float2(-1e30f, -1e30f);
        #pragma unroll
        for (int o = 8; o > 0; o >>= 1) {
            v.x = fmaxf(v.x, __shfl_xor_sync(0xFFFFFFFFu, v.x, o));
            v.y = fmaxf(v.y, __shfl_xor_sync(0xFFFFFFFFu, v.y, o));
        }
        if (lane == 0) red2[16] = v;
    }
    __syncthreads();
    float2 MX = red2[16];

    // exp + block sum
    float e0 = __expf(a0 - MX.x);
    float e1 = __expf(a1 - MX.y);
    pS2[tid] = make_float2(e0, e1);
    {
        float s0 = e0, s1 = e1;
        #pragma unroll
        for (int o = 16; o > 0; o >>= 1) {
            s0 += __shfl_xor_sync(0xFFFFFFFFu, s0, o);
            s1 += __shfl_xor_sync(0xFFFFFFFFu, s1, o);
        }
        if (lane == 0) red2[wid] = make_float2(s0, s1);
    }
    __syncthreads();
    if (tid < 32) {
        float2 v = (lane < 16) ? red2[lane] : make_float2(0.f, 0.f);
        #pragma unroll
        for (int o = 8; o > 0; o >>= 1) {
            v.x += __shfl_xor_sync(0xFFFFFFFFu, v.x, o);
            v.y += __shfl_xor_sync(0xFFFFFFFFu, v.y, o);
        }
        if (lane == 0) red2[17] = v;
    }
    __syncthreads();
    float2 SUM = red2[17];

    // retrieval: part[c][d] = sum over 64 m of p[m]*L[m][d]
    {
        int d = tid & 63, c = tid >> 6;   // 8 chunks of 64 m
        float r0 = 0.f, r1 = 0.f;
        int m0 = c * 64;
        #pragma unroll 8
        for (int mm = 0; mm < 64; mm++) {
            float2 p = pS2[m0 + mm];              // broadcast
            float  l = Lsm[(m0 + mm)*LSTR + d];   // conflict-free
            r0 += p.x*l; r1 += p.y*l;
        }
        part2[c*64 + d] = make_float2(r0, r1);
    }
    __syncthreads();
    if (tid < NTOK*DD) {
        int j = tid >> 6, d = tid & 63;
        const float* pf = (const float*)part2;
        float s = 0.f;
        #pragma unroll
        for (int c = 0; c < 8; c++)
            s += pf[(c*64 + d)*2 + j];
        float inv = 1.f / (j ? SUM.y : SUM.x);
        zqS[j*DD + d] = s * inv;                  // tmp[j][d] (zqS reused)
    }
    __syncthreads();

    // projection 1: s1[j][f] = sum_d tmp[j][d] * Wv[d][f]
    if (tid < NTOK*DD) {
        int j = tid >> 6, f = tid & 63;
        float s = 0.f;
        const float* tp = &zqS[j*DD];
        #pragma unroll 16
        for (int d = 0; d < DD; d++)
            s += tp[d] * WvS[d*DD + f];           // bcast + conflict-free
        s1S[j*DD + f] = s;
    }
    __syncthreads();

    // projection 2: out[j][e] = sum_f s1[j][f] * Wo[f][e]
    if (tid < NTOK*DD) {
        int j = tid >> 6, e = tid & 63;
        float o = 0.f;
        const float* sp = &s1S[j*DD];
        #pragma unroll 16
        for (int f = 0; f < DD; f++)
            o += sp[f] * WoS[f*DD + e];
        ((float*)&oS2[e])[j] = o;
    }
    __syncthreads();
    if (tid < DD) {
        float2 ov = oS2[tid];
        *(float2*)&out[(b*C2 + tid)*64 + n0] = ov;
    }
}

// ---------------------------------------------------------------------------
extern "C" void kernel_launch(void* const* d_in, const int* in_sizes, int n_in,
                              void* d_out, int out_size) {
    const float* x       = (const float*)d_in[0];
    const float* conv1_w = (const float*)d_in[1];
    const float* conv1_b = (const float*)d_in[2];
    const float* conv2_w = (const float*)d_in[3];
    const float* conv2_b = (const float*)d_in[4];
    const float* lookup  = (const float*)d_in[5];
    const float* Wv      = (const float*)d_in[6];
    const float* Wo      = (const float*)d_in[7];
    float* out = (float*)d_out;

    const size_t smem_bytes = SMEM_FLOATS * sizeof(float);

    cudaFuncSetAttribute(fused_kernel,
                         cudaFuncAttributeMaxDynamicSharedMemorySize,
                         (int)smem_bytes);
    cudaFuncSetAttribute(fused_kernel,
                         cudaFuncAttributePreferredSharedMemoryCarveout, 100);

    fused_kernel<<<NBLK, THR, smem_bytes>>>(
        x, conv1_w, conv1_b, conv2_w, conv2_b, lookup, Wv, Wo, out);
}

// round 14
// speedup vs baseline: 1.7287x; 1.0171x over previous
#include <cuda_runtime.h>

// Problem constants
#define BB   4      // batch
#define CIN  3
#define C1   32     // conv1 out channels (16x16 spatial)
#define C2   64     // conv2 out channels (8x8 spatial)
#define MM   512    // hopfield memory slots
#define DD   64     // token dim (== C2)
#define NTOK 2      // tokens per block
#define THR  512    // threads per block
#define NBLK 128    // 4 samples x 32 token-pairs; fully independent blocks
#define LSTR 68     // Lsm row stride (floats): 16B-aligned, conflict-free

// Shared memory layout (float offsets) — identical to the 17.2us baseline.
#define LSM_OFF   0                        // 512*68 = 34816
#define WVS_OFF   34816                    // 64*64  = 4096
#define WOS_OFF   38912                    // 64*64  = 4096
#define PS2_OFF   43008                    // 512 float2 = 1024 f
#define PART2_OFF 44032                    // 512 float2 = 1024 f
#define ZQ_OFF    45056                    // [2][64] tokens / tmp = 128 f
#define S1_OFF    45184                    // [2][64] = 128 f
#define OS2_OFF   45312                    // 64 float2 = 128 f
#define RED_OFF   45440                    // 40 f reduce scratch
#define XPAD_OFF  45480                    // 3*34*34 = 3468 f
#define AW_OFF    48948                    // 32*25 = 800 f (stride-25 conflict-free)
#define VW_OFF    49748                    // 32*25 = 800 f
#define SMEM_FLOATS 50548                  // 202192 bytes

__global__ __launch_bounds__(THR, 1)
void fused_kernel(const float* __restrict__ x,
                  const float* __restrict__ w1,
                  const float* __restrict__ b1,
                  const float* __restrict__ w2,
                  const float* __restrict__ b2,
                  const float* __restrict__ lookup,
                  const float* __restrict__ Wv,
                  const float* __restrict__ Wo,
                  float* __restrict__ out) {
    extern __shared__ float smem[];
    float*  Lsm   = smem + LSM_OFF;
    float*  WvS   = smem + WVS_OFF;
    float*  WoS   = smem + WOS_OFF;
    float2* pS2   = (float2*)(smem + PS2_OFF);
    float2* part2 = (float2*)(smem + PART2_OFF);
    float*  zqS   = smem + ZQ_OFF;        // [j][64]: tokens, later tmp
    float*  s1S   = smem + S1_OFF;        // [j][64]: first projection
    float2* oS2   = (float2*)(smem + OS2_OFF);
    float2* red2  = (float2*)(smem + RED_OFF);
    float*  xpad  = smem + XPAD_OFF;      // [3][34][34] zero-padded input
    float*  aW    = smem + AW_OFF;        // conv1 window, relu(pre)
    float*  vW    = smem + VW_OFF;        // conv1 window, masked JVP

    int tid  = threadIdx.x;
    int lane = tid & 31;
    int wid  = tid >> 5;
    int blk  = blockIdx.x;
    int b    = blk >> 5;                  // sample
    int tg   = blk & 31;                  // token group
    int n0   = tg * NTOK;
    int oy   = n0 >> 3;                   // both tokens share oy (n0 even)
    int ox0  = n0 & 7;

    // ===================================================================
    // Warp-specialized front end (R13):
    //   warps 0-7  (tid < 256): xpad halo-zero + interior stage + conv1
    //   warps 8-15 (tid >= 256): Lsm + Wv + Wo staging
    // ===================================================================
    if (tid < 256) {
        // --- halo-only zero (396 cells; disjoint from interior writes) ---
        for (int i = tid; i < 396; i += 256) {
            int p = i / 132, rem = i - p*132;
            int r, c;
            if (rem < 68) { r = (rem < 34) ? 0 : 33;
                            c = (rem < 34) ? rem : rem - 34; }
            else { int q = rem - 68; r = 1 + (q >> 1); c = (q & 1) * 33; }
            xpad[(p*34 + r)*34 + c] = 0.f;
        }
        // --- interior stage: 3072 floats / 256 threads = 12 each ---
        {
            const float* xb = x + b * CIN * 1024;
            #pragma unroll
            for (int it = 0; it < 12; it++) {
                int i = it*256 + tid;
                int ic = i >> 10, r = (i >> 5) & 31, c = i & 31;
                xpad[(ic*34 + r + 1)*34 + c + 1] = __ldg(&xb[i]);
            }
        }
        // conv-group barrier: warps 0-7 only (256 threads)
        asm volatile("bar.sync 1, 256;" ::: "memory");

        // --- Phase 1: conv1 for the 4x6 window (stride 256) ---
        for (int e = tid; e < 32*24; e += 256) {
            int ic  = e / 24;
            int pos = e - ic*24;
            int ri  = pos / 6;
            int ci  = pos - ri*6;
            int r = 2*oy - 1 + ri;
            int c = 2*ox0 - 1 + ci;
            float aVal = 0.f, vVal = 0.f;
            if ((unsigned)r < 16u && (unsigned)c < 16u) {
                float s = 0.f;
                #pragma unroll
                for (int cin = 0; cin < CIN; cin++) {
                    const float* base = &xpad[(cin*34 + 2*r)*34 + 2*c];
                    const float4* wp4 = (const float4*)&w1[(ic*CIN + cin)*16];
                    #pragma unroll
                    for (int ky = 0; ky < 4; ky++) {
                        float4 w4 = __ldg(&wp4[ky]);
                        const float* row = base + ky*34;
                        s += row[0]*w4.x + row[1]*w4.y + row[2]*w4.z + row[3]*w4.w;
                    }
                }
                float pre = s + __ldg(&b1[ic]);
                if (pre > 0.f) { aVal = pre; vVal = s; }
            }
            aW[ic*25 + pos] = aVal;
            vW[ic*25 + pos] = vVal;
        }
    } else {
        int t2 = tid - 256;                        // 0..255
        // --- Lsm staging: 8192 float4 / 256 thr = 32 each, MLP=8 batches ---
        const float4* L4   = (const float4*)lookup;
        float4*       Lsm4 = (float4*)Lsm;         // row stride 17 float4
        #pragma unroll
        for (int batch = 0; batch < 4; batch++) {
            float4 v[8];
            #pragma unroll
            for (int u = 0; u < 8; u++)
                v[u] = __ldg(&L4[(batch*8 + u)*256 + t2]);
            #pragma unroll
            for (int u = 0; u < 8; u++) {
                int f = (batch*8 + u)*256 + t2;    // float4 index
                Lsm4[(f >> 4)*17 + (f & 15)] = v[u];
            }
        }
        // --- Wv / Wo staging: 1024 float4 each / 256 thr = 4 each ---
        {
            const float4* Wv4 = (const float4*)Wv;
            const float4* Wo4 = (const float4*)Wo;
            #pragma unroll
            for (int u = 0; u < 4; u++) {
                ((float4*)WvS)[u*256 + t2] = __ldg(&Wv4[u*256 + t2]);
                ((float4*)WoS)[u*256 + t2] = __ldg(&Wo4[u*256 + t2]);
            }
        }
    }

    // --- conv2 w2 prefetch (group 1: ky = 0,1 for this warp's 4 oc) ---
    // Issued BEFORE the join so the LDG latency drains during the sync /
    // the other track's staging, instead of serially after it.
    const float4* w24 = (const float4*)w2;
    float4 wpre[8];
    {
        int ic = lane;
        #pragma unroll
        for (int o4 = 0; o4 < 4; o4++) {
            #pragma unroll
            for (int ky = 0; ky < 2; ky++)
                wpre[o4*2 + ky] = __ldg(&w24[((wid*4 + o4)*C1 + ic)*4 + ky]);
        }
    }
    __syncthreads();

    // ===== Phase 2: conv2 (R9 shape: warp->4 oc, lane->ic) ================
    {
        int ic = lane;
        float sA[4][2] = {}, sV[4][2] = {};
        // ky = 0,1 from prefetched regs
        #pragma unroll
        for (int ky = 0; ky < 2; ky++) {
            const float* ar = &aW[ic*25 + ky*6];
            const float* vr = &vW[ic*25 + ky*6];
            float a0=ar[0], a1=ar[1], a2=ar[2], a3=ar[3], a4=ar[4], a5=ar[5];
            float v0=vr[0], v1=vr[1], v2=vr[2], v3=vr[3], v4=vr[4], v5=vr[5];
            #pragma unroll
            for (int o4 = 0; o4 < 4; o4++) {
                float4 w4 = wpre[o4*2 + ky];
                sA[o4][0] += a0*w4.x + a1*w4.y + a2*w4.z + a3*w4.w;
                sV[o4][0] += v0*w4.x + v1*w4.y + v2*w4.z + v3*w4.w;
                sA[o4][1] += a2*w4.x + a3*w4.y + a4*w4.z + a5*w4.w;
                sV[o4][1] += v2*w4.x + v3*w4.y + v4*w4.z + v5*w4.w;
            }
        }
        // ky = 2,3 loaded here (latency covered by group-1 compute above)
        #pragma unroll
        for (int ky = 2; ky < 4; ky++) {
            const float* ar = &aW[ic*25 + ky*6];
            const float* vr = &vW[ic*25 + ky*6];
            float a0=ar[0], a1=ar[1], a2=ar[2], a3=ar[3], a4=ar[4], a5=ar[5];
            float v0=vr[0], v1=vr[1], v2=vr[2], v3=vr[3], v4=vr[4], v5=vr[5];
            #pragma unroll
            for (int o4 = 0; o4 < 4; o4++) {
                float4 w4 = __ldg(&w24[((wid*4 + o4)*C1 + ic)*4 + ky]);
                sA[o4][0] += a0*w4.x + a1*w4.y + a2*w4.z + a3*w4.w;
                sV[o4][0] += v0*w4.x + v1*w4.y + v2*w4.z + v3*w4.w;
                sA[o4][1] += a2*w4.x + a3*w4.y + a4*w4.z + a5*w4.w;
                sV[o4][1] += v2*w4.x + v3*w4.y + v4*w4.z + v5*w4.w;
            }
        }
        #pragma unroll
        for (int o4 = 0; o4 < 4; o4++)
            #pragma unroll
            for (int jj = 0; jj < 2; jj++)
                #pragma unroll
                for (int off = 16; off > 0; off >>= 1) {
                    sA[o4][jj] += __shfl_xor_sync(0xFFFFFFFFu, sA[o4][jj], off);
                    sV[o4][jj] += __shfl_xor_sync(0xFFFFFFFFu, sV[o4][jj], off);
                }
        if (lane == 0) {
            #pragma unroll
            for (int o4 = 0; o4 < 4; o4++) {
                int oc = wid*4 + o4;
                float bb = __ldg(&b2[oc]);
                #pragma unroll
                for (int jj = 0; jj < 2; jj++) {
                    float pre = sA[o4][jj] + bb;
                    zqS[jj*DD + oc] = (pre > 0.f) ? sV[o4][jj] : 0.f;
                }
            }
        }
    }
    __syncthreads();

    // ===== Phase 3: hopfield ==============================================
    // scores: thread owns row m = tid, both tokens
    float a0 = 0.f, a1 = 0.f;
    {
        const float4* lrow = (const float4*)&Lsm[tid*LSTR];
        const float4* t0p  = (const float4*)&zqS[0];
        const float4* t1p  = (const float4*)&zqS[DD];
        #pragma unroll
        for (int q = 0; q < 16; q++) {
            float4 l  = lrow[q];
            float4 t0 = t0p[q];
            float4 t1 = t1p[q];
            a0 += l.x*t0.x + l.y*t0.y + l.z*t0.z + l.w*t0.w;
            a1 += l.x*t1.x + l.y*t1.y + l.z*t1.z + l.w*t1.w;
        }
    }
    a0 *= 0.125f; a1 *= 0.125f;   // 1/sqrt(64)

    // block max: warp-reduce, store, one sync, every thread reduces locally
    {
        float mx0 = a0, mx1 = a1;
        #pragma unroll
        for (int o = 16; o > 0; o >>= 1) {
            mx0 = fmaxf(mx0, __shfl_xor_sync(0xFFFFFFFFu, mx0, o));
            mx1 = fmaxf(mx1, __shfl_xor_sync(0xFFFFFFFFu, mx1, o));
        }
        if (lane == 0) red2[wid] = make_float2(mx0, mx1);
    }
    __syncthreads();
    float2 MX;
    {
        float2 v = red2[0];
        #pragma unroll
        for (int w = 1; w < 16; w++) {
            float2 u = red2[w];
            v.x = fmaxf(v.x, u.x);
            v.y = fmaxf(v.y, u.y);
        }
        MX = v;
    }

    // exp + block sum (same local-reduce pattern)
    float e0 = __expf(a0 - MX.x);
    float e1 = __expf(a1 - MX.y);
    pS2[tid] = make_float2(e0, e1);
    {
        float s0 = e0, s1 = e1;
        #pragma unroll
        for (int o = 16; o > 0; o >>= 1) {
            s0 += __shfl_xor_sync(0xFFFFFFFFu, s0, o);
            s1 += __shfl_xor_sync(0xFFFFFFFFu, s1, o);
        }
        if (lane == 0) red2[16 + wid] = make_float2(s0, s1);
    }
    __syncthreads();
    float2 SUM;
    {
        float2 v = red2[16];
        #pragma unroll
        for (int w = 1; w < 16; w++) {
            float2 u = red2[16 + w];
            v.x += u.x;
            v.y += u.y;
        }
        SUM = v;
    }

    // retrieval: part[c][d] = sum over 64 m of p[m]*L[m][d]
    {
        int d = tid & 63, c = tid >> 6;   // 8 chunks of 64 m
        float r0 = 0.f, r1 = 0.f;
        int m0 = c * 64;
        #pragma unroll 8
        for (int mm = 0; mm < 64; mm++) {
            float2 p = pS2[m0 + mm];              // broadcast
            float  l = Lsm[(m0 + mm)*LSTR + d];   // conflict-free
            r0 += p.x*l; r1 += p.y*l;
        }
        part2[c*64 + d] = make_float2(r0, r1);
    }
    __syncthreads();
    if (tid < NTOK*DD) {
        int j = tid >> 6, d = tid & 63;
        const float* pf = (const float*)part2;
        float s = 0.f;
        #pragma unroll
        for (int c = 0; c < 8; c++)
            s += pf[(c*64 + d)*2 + j];
        float inv = 1.f / (j ? SUM.y : SUM.x);
        zqS[j*DD + d] = s * inv;                  // tmp[j][d] (zqS reused)
    }
    __syncthreads();

    // projection 1: s1[j][f] = sum_d tmp[j][d] * Wv[d][f]
    if (tid < NTOK*DD) {
        int j = tid >> 6, f = tid & 63;
        float s = 0.f;
        const float* tp = &zqS[j*DD];
        #pragma unroll 16
        for (int d = 0; d < DD; d++)
            s += tp[d] * WvS[d*DD + f];           // bcast + conflict-free
        s1S[j*DD + f] = s;
    }
    __syncthreads();

    // projection 2: out[j][e] = sum_f s1[j][f] * Wo[f][e]
    if (tid < NTOK*DD) {
        int j = tid >> 6, e = tid & 63;
        float o = 0.f;
        const float* sp = &s1S[j*DD];
        #pragma unroll 16
        for (int f = 0; f < DD; f++)
            o += sp[f] * WoS[f*DD + e];
        ((float*)&oS2[e])[j] = o;
    }
    __syncthreads();
    if (tid < DD) {
        float2 ov = oS2[tid];
        *(float2*)&out[(b*C2 + tid)*64 + n0] = ov;
    }
}

// ---------------------------------------------------------------------------
extern "C" void kernel_launch(void* const* d_in, const int* in_sizes, int n_in,
                              void* d_out, int out_size) {
    const float* x       = (const float*)d_in[0];
    const float* conv1_w = (const float*)d_in[1];
    const float* conv1_b = (const float*)d_in[2];
    const float* conv2_w = (const float*)d_in[3];
    const float* conv2_b = (const float*)d_in[4];
    const float* lookup  = (const float*)d_in[5];
    const float* Wv      = (const float*)d_in[6];
    const float* Wo      = (const float*)d_in[7];
    float* out = (float*)d_out;

    const size_t smem_bytes = SMEM_FLOATS * sizeof(float);

    cudaFuncSetAttribute(fused_kernel,
                         cudaFuncAttributeMaxDynamicSharedMemorySize,
                         (int)smem_bytes);
    cudaFuncSetAttribute(fused_kernel,
                         cudaFuncAttributePreferredSharedMemoryCarveout, 100);

    fused_kernel<<<NBLK, THR, smem_bytes>>>(
        x, conv1_w, conv1_b, conv2_w, conv2_b, lookup, Wv, Wo, out);
}